// round 8
// baseline (speedup 1.0000x reference)
#include <cuda_runtime.h>

#define N_VERTS 53215
#define EXP_DIM 29
#define SHP_DIM 199
#define SHP3    (3 * SHP_DIM)   // 597
#define EXP3    (3 * EXP_DIM)   // 87
#define ADIM    (SHP_DIM + EXP_DIM)  // 228

#define NTHREADS 256
#define WARPS_PER_BLOCK (NTHREADS / 32)

// ---------------------------------------------------------------------------
// R7 skeleton (forced front-batched loads, warp-per-vertex, 6652 blocks)
// + alphas staged in shared memory.
//
// Phase 0: one pass stages a_shp (228 = 199+29 floats) into smem.
// Phase 1: 22 streaming w-loads into a live register batch (__syncwarp fence
//          forces ptxas to emit them back-to-back: MLP ~22/warp, regs ~56).
// Phase 2: products use LDS alpha reads (consecutive banks, conflict-free) —
//          LDG count per vertex halves from 44 to 22, and the dependent FMA
//          chain waits on 29-cyc LDS instead of 39-cyc L1-hit LDG.
// Routing: only passes 6 and 12 straddle a row boundary; the rest constant-
//          fold at compile time.
//
// Transform (derived from _transform_matrix(pose, 450)):
//   s  = p3 + p7 + p11
//   ox = ( s*(p0x + p1y + p2z)  + p3)        * (224/450)
//   oy = (-s*(p4x + p5y + p6z)  - p7 + 450)  * (224/450)
//   oz =   s*(p8x + p9y + p10z)
// ---------------------------------------------------------------------------
__global__ void __launch_bounds__(NTHREADS, 4)
pca_smema_kernel(const float* __restrict__ pose,
                 const float* __restrict__ a_exp,
                 const float* __restrict__ a_shp,
                 const float* __restrict__ u,
                 const float* __restrict__ w_exp,
                 const float* __restrict__ w_shp,
                 float* __restrict__ out)
{
    __shared__ float s_a[ADIM];   // [0..198] = a_shp, [199..227] = a_exp

    const int t = threadIdx.x;
    if (t < ADIM)
        s_a[t] = (t < SHP_DIM) ? a_shp[t] : a_exp[t - SHP_DIM];
    __syncthreads();

    const int warp = (blockIdx.x * blockDim.x + t) >> 5;
    const int lane = t & 31;
    if (warp >= N_VERTS) return;

    const float* __restrict__ ws = w_shp + (size_t)warp * SHP3;
    const float* __restrict__ we = w_exp + (size_t)warp * EXP3;

    // ---- phase 1: front-batched independent loads (forced live: 22 regs) ----
    float w[22];
    #pragma unroll
    for (int i = 0; i < 19; i++) {
        const int j = i * 32 + lane;
        w[i] = (j < SHP3) ? __ldcs(ws + j) : 0.0f;
    }
    #pragma unroll
    for (int i = 0; i < 3; i++) {
        const int j = i * 32 + lane;
        w[19 + i] = (j < EXP3) ? __ldcs(we + j) : 0.0f;
    }

    __syncwarp();   // all w[] live across this point -> ptxas must batch loads

    // ---- phase 2: products with smem alpha reads, row routing ----
    float a0 = 0.f, a1 = 0.f, a2 = 0.f;

    #pragma unroll
    for (int i = 0; i < 19; i++) {
        const int j = i * 32 + lane;
        int col, row;
        if (j < SHP_DIM)          { col = j;               row = 0; }
        else if (j < 2 * SHP_DIM) { col = j - SHP_DIM;     row = 1; }
        else                      { col = j - 2 * SHP_DIM; row = 2; }
        if (col > SHP_DIM - 1) col = SHP_DIM - 1;   // w==0 there; keep in-bounds
        const float p = w[i] * s_a[col];
        if (row == 0)      a0 += p;
        else if (row == 1) a1 += p;
        else               a2 += p;
    }
    #pragma unroll
    for (int i = 0; i < 3; i++) {
        const int j = i * 32 + lane;
        int col, row;
        if (j < EXP_DIM)          { col = j;               row = 0; }
        else if (j < 2 * EXP_DIM) { col = j - EXP_DIM;     row = 1; }
        else                      { col = j - 2 * EXP_DIM; row = 2; }
        if (col > EXP_DIM - 1) col = EXP_DIM - 1;
        const float p = w[19 + i] * s_a[SHP_DIM + col];
        if (row == 0)      a0 += p;
        else if (row == 1) a1 += p;
        else               a2 += p;
    }

    // ---- warp reductions (3 values) ----
    #pragma unroll
    for (int off = 16; off > 0; off >>= 1) {
        a0 += __shfl_down_sync(0xffffffffu, a0, off);
        a1 += __shfl_down_sync(0xffffffffu, a1, off);
        a2 += __shfl_down_sync(0xffffffffu, a2, off);
    }

    if (lane == 0) {
        const float p0 = __ldg(pose + 0),  p1 = __ldg(pose + 1),  p2  = __ldg(pose + 2),  p3  = __ldg(pose + 3);
        const float p4 = __ldg(pose + 4),  p5 = __ldg(pose + 5),  p6  = __ldg(pose + 6),  p7  = __ldg(pose + 7);
        const float p8 = __ldg(pose + 8),  p9 = __ldg(pose + 9),  p10 = __ldg(pose + 10), p11 = __ldg(pose + 11);
        const float s  = p3 + p7 + p11;
        const float aspect_xy = 224.0f / 450.0f;

        const float x = a0 + __ldg(u + 3 * warp + 0);
        const float y = a1 + __ldg(u + 3 * warp + 1);
        const float z = a2 + __ldg(u + 3 * warp + 2);

        out[3 * warp + 0] = ( s * (p0 * x + p1 * y + p2  * z) + p3)          * aspect_xy;
        out[3 * warp + 1] = (-s * (p4 * x + p5 * y + p6  * z) - p7 + 450.0f) * aspect_xy;
        out[3 * warp + 2] =   s * (p8 * x + p9 * y + p10 * z);
    }
}

// ---------------------------------------------------------------------------
// Entry point
// Input order: pose_3DMM, alpha_exp, alpha_shp, u_base, w_exp_base, w_shp_base
// ---------------------------------------------------------------------------
extern "C" void kernel_launch(void* const* d_in, const int* in_sizes, int n_in,
                              void* d_out, int out_size)
{
    const float* pose  = (const float*)d_in[0];
    const float* a_exp = (const float*)d_in[1];
    const float* a_shp = (const float*)d_in[2];
    const float* u     = (const float*)d_in[3];
    const float* w_exp = (const float*)d_in[4];
    const float* w_shp = (const float*)d_in[5];
    float* out = (float*)d_out;

    const int blocks = (N_VERTS + WARPS_PER_BLOCK - 1) / WARPS_PER_BLOCK;
    pca_smema_kernel<<<blocks, NTHREADS>>>(pose, a_exp, a_shp, u, w_exp, w_shp, out);
}